// round 12
// baseline (speedup 1.0000x reference)
#include <cuda_runtime.h>
#include <cuda_bf16.h>
#include <math_constants.h>
#include <cstdint>

#define D 128
#define F 64
#define NSEG 912            // 6 CTAs/SM x 152 SMs = one wave
#define RED_CTAS 512
#define CHUNK (NSEG / 8)
// 4 * log2(e): logits produced in log2 units
#define SCALE_L2 5.770780163555854f
#define LN2 0.6931471805599453
#define LOSS_GRID 152
#define DSM_BYTES (16384 + 2 * 65536)   // sB + two 128-row fp32 tiles

// ---------------- scratch (no allocations allowed) ----------------
__device__ float  g_stage[NSEG * F * D];
__device__ float  g_part[8 * F * D];
__device__ uint2  g_bfrag[8 * 8 * 32];   // [kt][nt][lane], protos pre-scaled by 4*log2e/|s|
__device__ double g_loss;
__device__ int    g_ticket;

// ---------------- helpers ----------------
__device__ __forceinline__ unsigned pack_bf16x2(float lo, float hi) {
    unsigned r;
    asm("cvt.rn.bf16x2.f32 %0, %1, %2;" : "=r"(r) : "f"(hi), "f"(lo));
    return r;
}

__device__ __forceinline__ float ex2f(float x) {
    float r;
    asm("ex2.approx.f32 %0, %1;" : "=f"(r) : "f"(x));
    return r;
}

__device__ __forceinline__ void mma_bf16(float c[4],
                                         unsigned a0, unsigned a1, unsigned a2, unsigned a3,
                                         unsigned b0, unsigned b1) {
    asm volatile(
        "mma.sync.aligned.m16n8k16.row.col.f32.bf16.bf16.f32 "
        "{%0,%1,%2,%3}, {%4,%5,%6,%7}, {%8,%9}, {%0,%1,%2,%3};"
        : "+f"(c[0]), "+f"(c[1]), "+f"(c[2]), "+f"(c[3])
        : "r"(a0), "r"(a1), "r"(a2), "r"(a3), "r"(b0), "r"(b1));
}

// ---------------- K1: segment sums -> private slab (no counts needed) ----------------
#define G 8
__global__ __launch_bounds__(128) void k_segsum(const float* __restrict__ emb,
                                                const int* __restrict__ fams,
                                                int n) {
    __shared__ float acc[F * D];
    const int t = threadIdx.x;
    #pragma unroll
    for (int i = t; i < F * D; i += 128) acc[i] = 0.0f;
    __syncthreads();

    const int stride = gridDim.x;
    int r = blockIdx.x;

    int   cf[G]; float cv[G];
    int   nf[G]; float nv[G];

    if (r + (G - 1) * stride < n) {
        #pragma unroll
        for (int j = 0; j < G; j++) {
            cf[j] = fams[r + j * stride];
            cv[j] = emb[(size_t)(r + j * stride) * D + t];
        }
        int rn = r + G * stride;
        while (rn + (G - 1) * stride < n) {
            #pragma unroll
            for (int j = 0; j < G; j++) {
                nf[j] = fams[rn + j * stride];
                nv[j] = emb[(size_t)(rn + j * stride) * D + t];
            }
            #pragma unroll
            for (int j = 0; j < G; j++) acc[cf[j] * D + t] += cv[j];
            #pragma unroll
            for (int j = 0; j < G; j++) { cf[j] = nf[j]; cv[j] = nv[j]; }
            rn += G * stride;
        }
        #pragma unroll
        for (int j = 0; j < G; j++) acc[cf[j] * D + t] += cv[j];
        r = rn;
    }
    for (; r < n; r += stride)
        acc[fams[r] * D + t] += emb[(size_t)r * D + t];

    __syncthreads();
    float* st = g_stage + (size_t)blockIdx.x * (F * D);
    #pragma unroll
    for (int i = t; i < F * D; i += 128) st[i] = acc[i];
}

// ---------------- K1b: reduce slabs -> 8 non-atomic partials ----------------
__global__ __launch_bounds__(128) void k_reduce() {
    const int t  = threadIdx.x;
    const int dg = blockIdx.x & 63;
    const int cg = blockIdx.x >> 6;
    const int base = dg * 128 + t;
    const int c0 = cg * CHUNK, c1 = c0 + CHUNK;
    float s = 0.0f;
    int c = c0;
    for (; c + 7 < c1; c += 8) {
        float v0 = g_stage[(size_t)(c + 0) * (F * D) + base];
        float v1 = g_stage[(size_t)(c + 1) * (F * D) + base];
        float v2 = g_stage[(size_t)(c + 2) * (F * D) + base];
        float v3 = g_stage[(size_t)(c + 3) * (F * D) + base];
        float v4 = g_stage[(size_t)(c + 4) * (F * D) + base];
        float v5 = g_stage[(size_t)(c + 5) * (F * D) + base];
        float v6 = g_stage[(size_t)(c + 6) * (F * D) + base];
        float v7 = g_stage[(size_t)(c + 7) * (F * D) + base];
        s += ((v0 + v1) + (v2 + v3)) + ((v4 + v5) + (v6 + v7));
    }
    for (; c < c1; c++) s += g_stage[(size_t)c * (F * D) + base];
    g_part[cg * (F * D) + base] = s;
}

// ---------------- K2: normalized protos -> bf16 B-fragments ----------------
__global__ __launch_bounds__(128) void k_protos() {
    __shared__ float sp[D];
    __shared__ float red[4];
    const int f = blockIdx.x;
    const int t = threadIdx.x;

    if (f == 0 && t == 0) { g_loss = 0.0; g_ticket = 0; }

    float s = 0.0f;
    #pragma unroll
    for (int cg = 0; cg < 8; cg++) s += g_part[cg * (F * D) + f * D + t];

    float q = s * s;
    #pragma unroll
    for (int o = 16; o > 0; o >>= 1) q += __shfl_xor_sync(0xffffffffu, q, o);
    if ((t & 31) == 0) red[t >> 5] = q;
    __syncthreads();
    const float ssum = (red[0] + red[1]) + (red[2] + red[3]);
    const float pinv = SCALE_L2 / fmaxf(sqrtf(ssum), 1e-9f);
    sp[t] = s * pinv;
    __syncthreads();

    if (t < 32) {
        const int kt = t >> 2;
        const int c  = t & 3;
        const int k0 = kt * 16 + c * 4;
        uint2 b;
        b.x = pack_bf16x2(sp[k0],     sp[k0 + 1]);
        b.y = pack_bf16x2(sp[k0 + 2], sp[k0 + 3]);
        g_bfrag[(kt * 8 + (f >> 3)) * 32 + (f & 7) * 4 + c] = b;
    }
}

// ---------------- K3: cp.async-staged fused dots + cosine + LSE + loss ----------------
// 1 CTA/SM, 256 threads, 128-row (64KB) fp32 tiles, depth-2 cp.async pipeline.
// Conflict-free smem layout: chunk (row r, 16B-chunk cg) at
//   (cg>>2)*8192 + (cg&3)*128 + (r&7)*16 + (r>>3)*512
// Both stores and per-kt LDS.128 reads hit 32 distinct 16B slots mod 512.
__global__ __launch_bounds__(256, 1) void k_loss(const float* __restrict__ emb,
                                                 const int* __restrict__ fams,
                                                 int n, float* __restrict__ out) {
    extern __shared__ unsigned char dsm[];
    uint2* sB = reinterpret_cast<uint2*>(dsm);
    __shared__ float sRed[8];

    const int t = threadIdx.x;
    const int lane = t & 31, w = t >> 5;
    const int ntiles = n >> 7;
    const int grid = gridDim.x;

    uint32_t buf_u32;
    {
        unsigned char* bp = dsm + 16384;
        asm("{ .reg .u64 tmp; cvta.to.shared.u64 tmp, %1; cvt.u32.u64 %0, tmp; }"
            : "=r"(buf_u32) : "l"(bp));
    }

    // stage one 128-row tile into buffer kbuf (all 256 threads; 16 chunks each)
    auto stage = [&](int tile, int kbuf) {
        if (tile < ntiles) {
            const char* sbase = reinterpret_cast<const char*>(emb)
                              + (size_t)tile * (128 * 512)
                              + (w * 16 + (lane >> 2)) * 512 + (lane & 3) * 16;
            const uint32_t dbase = buf_u32 + kbuf * 65536
                                 + (lane & 3) * 128 + (lane >> 2) * 16 + w * 1024;
            #pragma unroll
            for (int i = 0; i < 16; i++) {
                uint32_t d = dbase + (i >> 1) * 8192 + (i & 1) * 512;
                const char* s = sbase + (i & 1) * 4096 + (i >> 1) * 64;
                asm volatile("cp.async.cg.shared.global [%0], [%1], 16;"
                             :: "r"(d), "l"(s));
            }
        }
        asm volatile("cp.async.commit_group;" ::: "memory");
    };

    // prologue: two tiles in flight
    stage(blockIdx.x, 0);
    stage(blockIdx.x + grid, 1);

    for (int i = t; i < 8 * 8 * 32; i += 256) sB[i] = g_bfrag[i];

    float lsum = 0.0f;
    int kbuf = 0;
    for (int tile = blockIdx.x; tile < ntiles; tile += grid, kbuf ^= 1) {
        asm volatile("cp.async.wait_group 1;" ::: "memory");
        __syncthreads();   // publishes staged tile (and sB on first pass)

        const int rg = (tile << 7) + w * 16 + (lane >> 2);
        const int f0 = fams[rg];
        const int f1 = fams[rg + 8];
        const uint32_t abase = buf_u32 + kbuf * 65536
                             + (lane & 3) * 128 + (lane >> 2) * 16 + w * 1024;

        float acc[8][4];
        #pragma unroll
        for (int nt = 0; nt < 8; nt++)
            #pragma unroll
            for (int j = 0; j < 4; j++) acc[nt][j] = 0.0f;

        float ss0 = 0.0f, ss1 = 0.0f;

        #pragma unroll
        for (int kt = 0; kt < 8; kt++) {
            float4 c0, c1;
            asm("ld.shared.v4.f32 {%0,%1,%2,%3}, [%4];"
                : "=f"(c0.x), "=f"(c0.y), "=f"(c0.z), "=f"(c0.w)
                : "r"(abase + kt * 8192));
            asm("ld.shared.v4.f32 {%0,%1,%2,%3}, [%4];"
                : "=f"(c1.x), "=f"(c1.y), "=f"(c1.z), "=f"(c1.w)
                : "r"(abase + kt * 8192 + 512));
            ss0 += c0.x * c0.x + c0.y * c0.y + c0.z * c0.z + c0.w * c0.w;
            ss1 += c1.x * c1.x + c1.y * c1.y + c1.z * c1.z + c1.w * c1.w;
            unsigned a0 = pack_bf16x2(c0.x, c0.y);
            unsigned a2 = pack_bf16x2(c0.z, c0.w);
            unsigned a1 = pack_bf16x2(c1.x, c1.y);
            unsigned a3 = pack_bf16x2(c1.z, c1.w);
            #pragma unroll
            for (int nt = 0; nt < 8; nt++) {
                uint2 b = sB[(kt * 8 + nt) * 32 + lane];
                mma_bf16(acc[nt], a0, a1, a2, a3, b.x, b.y);
            }
        }

        ss0 += __shfl_xor_sync(0xffffffffu, ss0, 1);
        ss0 += __shfl_xor_sync(0xffffffffu, ss0, 2);
        ss1 += __shfl_xor_sync(0xffffffffu, ss1, 1);
        ss1 += __shfl_xor_sync(0xffffffffu, ss1, 2);
        const float ie0 = rsqrtf(ss0);
        const float ie1 = rsqrtf(ss1);

        // logits in log2 units (scale pre-folded into B); |l| <= 5.78, no max-sub needed
        float pos0 = 0.0f, pos1 = 0.0f;
        float sum0 = 0.0f, sum1 = 0.0f;
        const int cbase = (lane & 3) * 2;

        #pragma unroll
        for (int nt = 0; nt < 8; nt++) {
            #pragma unroll
            for (int j = 0; j < 2; j++) {
                const int col = nt * 8 + cbase + j;
                float l0 = acc[nt][j]     * ie0;
                float l1 = acc[nt][2 + j] * ie1;
                sum0 += ex2f(l0);
                sum1 += ex2f(l1);
                if (col == f0) pos0 = l0;
                if (col == f1) pos1 = l1;
            }
        }
        pos0 += __shfl_xor_sync(0xffffffffu, pos0, 1);
        pos0 += __shfl_xor_sync(0xffffffffu, pos0, 2);
        pos1 += __shfl_xor_sync(0xffffffffu, pos1, 1);
        pos1 += __shfl_xor_sync(0xffffffffu, pos1, 2);
        sum0 += __shfl_xor_sync(0xffffffffu, sum0, 1);
        sum0 += __shfl_xor_sync(0xffffffffu, sum0, 2);
        sum1 += __shfl_xor_sync(0xffffffffu, sum1, 1);
        sum1 += __shfl_xor_sync(0xffffffffu, sum1, 2);

        if ((lane & 3) == 0) {
            lsum += (-0.5f * pos0 + __log2f(sum0))
                  + (-0.5f * pos1 + __log2f(sum1));
        }

        __syncthreads();             // all warps done reading this buffer
        stage(tile + 2 * grid, kbuf);
    }

    #pragma unroll
    for (int o = 16; o > 0; o >>= 1) lsum += __shfl_xor_sync(0xffffffffu, lsum, o);
    if (lane == 0) sRed[w] = lsum;
    __syncthreads();
    if (t == 0) {
        float s = 0.0f;
        #pragma unroll
        for (int q = 0; q < 8; q++) s += sRed[q];
        atomicAdd(&g_loss, (double)s);
        __threadfence();
        int v = atomicAdd(&g_ticket, 1);
        if (v == (int)gridDim.x - 1) {
            double total = atomicAdd(&g_loss, 0.0);
            out[0] = (float)(total * LN2 / (double)n);
        }
    }
}

// ---------------- launch ----------------
extern "C" void kernel_launch(void* const* d_in, const int* in_sizes, int n_in,
                              void* d_out, int out_size) {
    const float* emb  = (const float*)d_in[0];
    const int*   fams = (const int*)d_in[1];
    const int n = in_sizes[1];
    float* out = (float*)d_out;

    cudaFuncSetAttribute(k_loss, cudaFuncAttributeMaxDynamicSharedMemorySize, DSM_BYTES);

    k_segsum<<<NSEG, 128>>>(emb, fams, n);
    k_reduce<<<RED_CTAS, 128>>>();
    k_protos<<<F, 128>>>();
    k_loss<<<LOSS_GRID, 256, DSM_BYTES>>>(emb, fams, n, out);
}

// round 13
// speedup vs baseline: 1.2719x; 1.2719x over previous
#include <cuda_runtime.h>
#include <cuda_bf16.h>
#include <math_constants.h>
#include <cstdint>

#define D 128
#define F 64
#define NSEG 912            // 6 CTAs/SM x 152 SMs = one wave
#define RED_CTAS 512
#define CHUNK (NSEG / 8)
// 4 * log2(e): logits produced in log2 units
#define SCALE_L2 5.770780163555854f
#define LN2 0.6931471805599453
#define LOSS_GRID 304       // 2 CTAs/SM
#define LOSS_WARPS (LOSS_GRID * 8)

// ---------------- scratch (no allocations allowed) ----------------
__device__ float  g_stage[NSEG * F * D];
__device__ float  g_part[8 * F * D];
__device__ uint2  g_bfrag[8 * 8 * 32];   // [kt][nt][lane], protos pre-scaled by 4*log2e/|s|
__device__ double g_loss;
__device__ int    g_ticket;
__device__ int    g_work;                // work-stealing counter (double-wb units)

// ---------------- helpers ----------------
__device__ __forceinline__ unsigned pack_bf16x2(float lo, float hi) {
    unsigned r;
    asm("cvt.rn.bf16x2.f32 %0, %1, %2;" : "=r"(r) : "f"(hi), "f"(lo));
    return r;
}

__device__ __forceinline__ float ex2f(float x) {
    float r;
    asm("ex2.approx.f32 %0, %1;" : "=f"(r) : "f"(x));
    return r;
}

__device__ __forceinline__ void mma_bf16(float c[4],
                                         unsigned a0, unsigned a1, unsigned a2, unsigned a3,
                                         unsigned b0, unsigned b1) {
    asm volatile(
        "mma.sync.aligned.m16n8k16.row.col.f32.bf16.bf16.f32 "
        "{%0,%1,%2,%3}, {%4,%5,%6,%7}, {%8,%9}, {%0,%1,%2,%3};"
        : "+f"(c[0]), "+f"(c[1]), "+f"(c[2]), "+f"(c[3])
        : "r"(a0), "r"(a1), "r"(a2), "r"(a3), "r"(b0), "r"(b1));
}

// ---------------- K1: segment sums -> private slab (no counts needed) ----------------
#define G 8
__global__ __launch_bounds__(128) void k_segsum(const float* __restrict__ emb,
                                                const int* __restrict__ fams,
                                                int n) {
    __shared__ float acc[F * D];
    const int t = threadIdx.x;
    #pragma unroll
    for (int i = t; i < F * D; i += 128) acc[i] = 0.0f;
    __syncthreads();

    const int stride = gridDim.x;
    int r = blockIdx.x;

    int   cf[G]; float cv[G];
    int   nf[G]; float nv[G];

    if (r + (G - 1) * stride < n) {
        #pragma unroll
        for (int j = 0; j < G; j++) {
            cf[j] = fams[r + j * stride];
            cv[j] = emb[(size_t)(r + j * stride) * D + t];
        }
        int rn = r + G * stride;
        while (rn + (G - 1) * stride < n) {
            #pragma unroll
            for (int j = 0; j < G; j++) {
                nf[j] = fams[rn + j * stride];
                nv[j] = emb[(size_t)(rn + j * stride) * D + t];
            }
            #pragma unroll
            for (int j = 0; j < G; j++) acc[cf[j] * D + t] += cv[j];
            #pragma unroll
            for (int j = 0; j < G; j++) { cf[j] = nf[j]; cv[j] = nv[j]; }
            rn += G * stride;
        }
        #pragma unroll
        for (int j = 0; j < G; j++) acc[cf[j] * D + t] += cv[j];
        r = rn;
    }
    for (; r < n; r += stride)
        acc[fams[r] * D + t] += emb[(size_t)r * D + t];

    __syncthreads();
    float* st = g_stage + (size_t)blockIdx.x * (F * D);
    #pragma unroll
    for (int i = t; i < F * D; i += 128) st[i] = acc[i];
}

// ---------------- K1b: reduce slabs -> 8 non-atomic partials ----------------
__global__ __launch_bounds__(128) void k_reduce() {
    const int t  = threadIdx.x;
    const int dg = blockIdx.x & 63;
    const int cg = blockIdx.x >> 6;
    const int base = dg * 128 + t;
    const int c0 = cg * CHUNK, c1 = c0 + CHUNK;
    float s = 0.0f;
    int c = c0;
    for (; c + 7 < c1; c += 8) {
        float v0 = g_stage[(size_t)(c + 0) * (F * D) + base];
        float v1 = g_stage[(size_t)(c + 1) * (F * D) + base];
        float v2 = g_stage[(size_t)(c + 2) * (F * D) + base];
        float v3 = g_stage[(size_t)(c + 3) * (F * D) + base];
        float v4 = g_stage[(size_t)(c + 4) * (F * D) + base];
        float v5 = g_stage[(size_t)(c + 5) * (F * D) + base];
        float v6 = g_stage[(size_t)(c + 6) * (F * D) + base];
        float v7 = g_stage[(size_t)(c + 7) * (F * D) + base];
        s += ((v0 + v1) + (v2 + v3)) + ((v4 + v5) + (v6 + v7));
    }
    for (; c < c1; c++) s += g_stage[(size_t)c * (F * D) + base];
    g_part[cg * (F * D) + base] = s;
}

// ---------------- K2: normalized protos -> bf16 B-fragments ----------------
__global__ __launch_bounds__(128) void k_protos() {
    __shared__ float sp[D];
    __shared__ float red[4];
    const int f = blockIdx.x;
    const int t = threadIdx.x;

    if (f == 0 && t == 0) { g_loss = 0.0; g_ticket = 0; g_work = LOSS_WARPS; }

    float s = 0.0f;
    #pragma unroll
    for (int cg = 0; cg < 8; cg++) s += g_part[cg * (F * D) + f * D + t];

    float q = s * s;
    #pragma unroll
    for (int o = 16; o > 0; o >>= 1) q += __shfl_xor_sync(0xffffffffu, q, o);
    if ((t & 31) == 0) red[t >> 5] = q;
    __syncthreads();
    const float ssum = (red[0] + red[1]) + (red[2] + red[3]);
    const float pinv = SCALE_L2 / fmaxf(sqrtf(ssum), 1e-9f);
    sp[t] = s * pinv;
    __syncthreads();

    if (t < 32) {
        const int kt = t >> 2;
        const int c  = t & 3;
        const int k0 = kt * 16 + c * 4;
        uint2 b;
        b.x = pack_bf16x2(sp[k0],     sp[k0 + 1]);
        b.y = pack_bf16x2(sp[k0 + 2], sp[k0 + 3]);
        g_bfrag[(kt * 8 + (f >> 3)) * 32 + (f & 7) * 4 + c] = b;
    }
}

// ---------------- K3: fused dots + cosine + LSE + loss, 32 rows/warp/iter ----------------
// 2 CTAs/SM, per-warp register pipeline (depth-2, 4 float4/kt in flight),
// warp-level work stealing over 32-row double-warp-blocks.
__global__ __launch_bounds__(256, 2) void k_loss(const float* __restrict__ emb,
                                                 const int* __restrict__ fams,
                                                 int n, float* __restrict__ out) {
    __shared__ uint2 sB[8 * 8 * 32];   // 16 KB
    __shared__ float sRed[8];
    const int t = threadIdx.x;
    for (int i = t; i < 8 * 8 * 32; i += 256) sB[i] = g_bfrag[i];
    __syncthreads();

    const int lane = t & 31, wid = t >> 5;
    const int ndwb = n >> 5;                 // 32-row units
    const int roff = (lane >> 2);
    const int koff = (lane & 3) * 4;

    float lsum = 0.0f;

    int dwb = blockIdx.x * 8 + wid;          // first unit = global warp id
    const float* p = emb;
    float4 buf[2][4];                        // [slot][row group 0..3]

    if (dwb < ndwb) {
        p = emb + (size_t)((dwb << 5) + roff) * D + koff;
        #pragma unroll
        for (int q = 0; q < 2; q++)
            #pragma unroll
            for (int j = 0; j < 4; j++)
                buf[q][j] = *(const float4*)(p + q * 16 + j * 1024);
    }

    while (dwb < ndwb) {
        // steal next unit early; latency (ATOMG ~318cyc) hidden by the kt loop
        int next_raw = 0;
        if (lane == 0) next_raw = atomicAdd(&g_work, 1);

        const int rbase = dwb << 5;
        const int f0 = fams[rbase + roff];
        const int f1 = fams[rbase + roff + 8];
        const int f2 = fams[rbase + roff + 16];
        const int f3 = fams[rbase + roff + 24];

        float accA[8][4], accB[8][4];
        #pragma unroll
        for (int nt = 0; nt < 8; nt++)
            #pragma unroll
            for (int j = 0; j < 4; j++) { accA[nt][j] = 0.0f; accB[nt][j] = 0.0f; }

        float ssv[4] = {0.f, 0.f, 0.f, 0.f};
        int next = ndwb;
        const float* np = p;

        #pragma unroll
        for (int kt = 0; kt < 8; kt++) {
            const int sl = kt & 1;
            float4 c0 = buf[sl][0], c1 = buf[sl][1], c2 = buf[sl][2], c3 = buf[sl][3];
            if (kt < 6) {
                #pragma unroll
                for (int j = 0; j < 4; j++)
                    buf[sl][j] = *(const float4*)(p + (kt + 2) * 16 + j * 1024);
            } else {
                if (kt == 6) {
                    next = __shfl_sync(0xffffffffu, next_raw, 0);
                    if (next < ndwb)
                        np = emb + (size_t)((next << 5) + roff) * D + koff;
                }
                if (next < ndwb) {
                    const int q = kt - 6;
                    #pragma unroll
                    for (int j = 0; j < 4; j++)
                        buf[sl][j] = *(const float4*)(np + q * 16 + j * 1024);
                }
            }
            ssv[0] += c0.x * c0.x + c0.y * c0.y + c0.z * c0.z + c0.w * c0.w;
            ssv[1] += c1.x * c1.x + c1.y * c1.y + c1.z * c1.z + c1.w * c1.w;
            ssv[2] += c2.x * c2.x + c2.y * c2.y + c2.z * c2.z + c2.w * c2.w;
            ssv[3] += c3.x * c3.x + c3.y * c3.y + c3.z * c3.z + c3.w * c3.w;
            unsigned a0 = pack_bf16x2(c0.x, c0.y);
            unsigned a2 = pack_bf16x2(c0.z, c0.w);
            unsigned a1 = pack_bf16x2(c1.x, c1.y);
            unsigned a3 = pack_bf16x2(c1.z, c1.w);
            unsigned a4 = pack_bf16x2(c2.x, c2.y);
            unsigned a6 = pack_bf16x2(c2.z, c2.w);
            unsigned a5 = pack_bf16x2(c3.x, c3.y);
            unsigned a7 = pack_bf16x2(c3.z, c3.w);
            #pragma unroll
            for (int nt = 0; nt < 8; nt++) {
                uint2 b = sB[(kt * 8 + nt) * 32 + lane];
                mma_bf16(accA[nt], a0, a1, a2, a3, b.x, b.y);
                mma_bf16(accB[nt], a4, a5, a6, a7, b.x, b.y);
            }
        }

        #pragma unroll
        for (int j = 0; j < 4; j++) {
            ssv[j] += __shfl_xor_sync(0xffffffffu, ssv[j], 1);
            ssv[j] += __shfl_xor_sync(0xffffffffu, ssv[j], 2);
        }
        const float ie0 = rsqrtf(ssv[0]);
        const float ie1 = rsqrtf(ssv[1]);
        const float ie2 = rsqrtf(ssv[2]);
        const float ie3 = rsqrtf(ssv[3]);

        // logits in log2 units; |l| <= 5.78, no max-sub needed
        float pos[4] = {0.f, 0.f, 0.f, 0.f};
        float sum[4] = {0.f, 0.f, 0.f, 0.f};
        const int cbase = (lane & 3) * 2;

        #pragma unroll
        for (int nt = 0; nt < 8; nt++) {
            #pragma unroll
            for (int j = 0; j < 2; j++) {
                const int col = nt * 8 + cbase + j;
                float l0 = accA[nt][j]     * ie0;
                float l1 = accA[nt][2 + j] * ie1;
                float l2 = accB[nt][j]     * ie2;
                float l3 = accB[nt][2 + j] * ie3;
                sum[0] += ex2f(l0);
                sum[1] += ex2f(l1);
                sum[2] += ex2f(l2);
                sum[3] += ex2f(l3);
                if (col == f0) pos[0] = l0;
                if (col == f1) pos[1] = l1;
                if (col == f2) pos[2] = l2;
                if (col == f3) pos[3] = l3;
            }
        }
        #pragma unroll
        for (int j = 0; j < 4; j++) {
            pos[j] += __shfl_xor_sync(0xffffffffu, pos[j], 1);
            pos[j] += __shfl_xor_sync(0xffffffffu, pos[j], 2);
            sum[j] += __shfl_xor_sync(0xffffffffu, sum[j], 1);
            sum[j] += __shfl_xor_sync(0xffffffffu, sum[j], 2);
        }

        if ((lane & 3) == 0) {
            lsum += (-0.5f * pos[0] + __log2f(sum[0]))
                  + (-0.5f * pos[1] + __log2f(sum[1]))
                  + (-0.5f * pos[2] + __log2f(sum[2]))
                  + (-0.5f * pos[3] + __log2f(sum[3]));
        }

        dwb = next;
        p = np;
    }

    #pragma unroll
    for (int o = 16; o > 0; o >>= 1) lsum += __shfl_xor_sync(0xffffffffu, lsum, o);
    if (lane == 0) sRed[wid] = lsum;
    __syncthreads();
    if (t == 0) {
        float s = 0.0f;
        #pragma unroll
        for (int q = 0; q < 8; q++) s += sRed[q];
        atomicAdd(&g_loss, (double)s);
        __threadfence();
        int v = atomicAdd(&g_ticket, 1);
        if (v == (int)gridDim.x - 1) {
            double total = atomicAdd(&g_loss, 0.0);
            out[0] = (float)(total * LN2 / (double)n);
        }
    }
}

// ---------------- launch ----------------
extern "C" void kernel_launch(void* const* d_in, const int* in_sizes, int n_in,
                              void* d_out, int out_size) {
    const float* emb  = (const float*)d_in[0];
    const int*   fams = (const int*)d_in[1];
    const int n = in_sizes[1];
    float* out = (float*)d_out;

    k_segsum<<<NSEG, 128>>>(emb, fams, n);
    k_reduce<<<RED_CTAS, 128>>>();
    k_protos<<<F, 128>>>();
    k_loss<<<LOSS_GRID, 256>>>(emb, fams, n, out);
}

// round 14
// speedup vs baseline: 1.3176x; 1.0359x over previous
#include <cuda_runtime.h>
#include <cuda_bf16.h>
#include <math_constants.h>
#include <cstdint>

#define D 128
#define F 64
#define NSEG 912            // 6 CTAs/SM x 152 SMs = one wave
#define RED_CTAS 512
#define CHUNK (NSEG / 8)
// 4 * log2(e): logits produced in log2 units
#define SCALE_L2 5.770780163555854f
#define LN2 0.6931471805599453

// ---------------- scratch (no allocations allowed) ----------------
__device__ float  g_stage[NSEG * F * D];
__device__ float  g_part[8 * F * D];
__device__ uint4  g_bfrag4[8 * 4 * 32];  // [kt][nt-pair][lane]: {b(2m).x,b(2m).y,b(2m+1).x,b(2m+1).y}
__device__ double g_loss;
__device__ int    g_ticket;

// ---------------- helpers ----------------
__device__ __forceinline__ unsigned pack_bf16x2(float lo, float hi) {
    unsigned r;
    asm("cvt.rn.bf16x2.f32 %0, %1, %2;" : "=r"(r) : "f"(hi), "f"(lo));
    return r;
}

__device__ __forceinline__ float ex2f(float x) {
    float r;
    asm("ex2.approx.f32 %0, %1;" : "=f"(r) : "f"(x));
    return r;
}

__device__ __forceinline__ void mma_bf16(float c[4],
                                         unsigned a0, unsigned a1, unsigned a2, unsigned a3,
                                         unsigned b0, unsigned b1) {
    asm volatile(
        "mma.sync.aligned.m16n8k16.row.col.f32.bf16.bf16.f32 "
        "{%0,%1,%2,%3}, {%4,%5,%6,%7}, {%8,%9}, {%0,%1,%2,%3};"
        : "+f"(c[0]), "+f"(c[1]), "+f"(c[2]), "+f"(c[3])
        : "r"(a0), "r"(a1), "r"(a2), "r"(a3), "r"(b0), "r"(b1));
}

// ---------------- K1: segment sums -> private slab, depth-16 prefetch ----------------
#define G 16
__global__ __launch_bounds__(128) void k_segsum(const float* __restrict__ emb,
                                                const int* __restrict__ fams,
                                                int n) {
    __shared__ float acc[F * D];
    const int t = threadIdx.x;
    #pragma unroll
    for (int i = t; i < F * D; i += 128) acc[i] = 0.0f;
    __syncthreads();

    const int stride = gridDim.x;
    int r = blockIdx.x;

    int   cf[G]; float cv[G];
    int   nf[G]; float nv[G];

    if (r + (G - 1) * stride < n) {
        #pragma unroll
        for (int j = 0; j < G; j++) {
            cf[j] = fams[r + j * stride];
            cv[j] = emb[(size_t)(r + j * stride) * D + t];
        }
        int rn = r + G * stride;
        while (rn + (G - 1) * stride < n) {
            #pragma unroll
            for (int j = 0; j < G; j++) {
                nf[j] = fams[rn + j * stride];
                nv[j] = emb[(size_t)(rn + j * stride) * D + t];
            }
            #pragma unroll
            for (int j = 0; j < G; j++) acc[cf[j] * D + t] += cv[j];
            #pragma unroll
            for (int j = 0; j < G; j++) { cf[j] = nf[j]; cv[j] = nv[j]; }
            rn += G * stride;
        }
        #pragma unroll
        for (int j = 0; j < G; j++) acc[cf[j] * D + t] += cv[j];
        r = rn;
    }
    for (; r < n; r += stride)
        acc[fams[r] * D + t] += emb[(size_t)r * D + t];

    __syncthreads();
    float* st = g_stage + (size_t)blockIdx.x * (F * D);
    #pragma unroll
    for (int i = t; i < F * D; i += 128) st[i] = acc[i];
}

// ---------------- K1b: reduce slabs -> 8 non-atomic partials ----------------
__global__ __launch_bounds__(128) void k_reduce() {
    const int t  = threadIdx.x;
    const int dg = blockIdx.x & 63;
    const int cg = blockIdx.x >> 6;
    const int base = dg * 128 + t;
    const int c0 = cg * CHUNK, c1 = c0 + CHUNK;
    float s = 0.0f;
    int c = c0;
    for (; c + 7 < c1; c += 8) {
        float v0 = g_stage[(size_t)(c + 0) * (F * D) + base];
        float v1 = g_stage[(size_t)(c + 1) * (F * D) + base];
        float v2 = g_stage[(size_t)(c + 2) * (F * D) + base];
        float v3 = g_stage[(size_t)(c + 3) * (F * D) + base];
        float v4 = g_stage[(size_t)(c + 4) * (F * D) + base];
        float v5 = g_stage[(size_t)(c + 5) * (F * D) + base];
        float v6 = g_stage[(size_t)(c + 6) * (F * D) + base];
        float v7 = g_stage[(size_t)(c + 7) * (F * D) + base];
        s += ((v0 + v1) + (v2 + v3)) + ((v4 + v5) + (v6 + v7));
    }
    for (; c < c1; c++) s += g_stage[(size_t)c * (F * D) + base];
    g_part[cg * (F * D) + base] = s;
}

// ---------------- K2: normalized protos -> paired bf16 B-fragments ----------------
// grid = 64 CTAs (one per family), 128 threads (one per dim).
// Cosine is scale-invariant: counts cancel. Fold 4*log2e/|s_f| into fragments.
__global__ __launch_bounds__(128) void k_protos() {
    __shared__ float sp[D];
    __shared__ float red[4];
    const int f = blockIdx.x;
    const int t = threadIdx.x;

    if (f == 0 && t == 0) { g_loss = 0.0; g_ticket = 0; }

    float s = 0.0f;
    #pragma unroll
    for (int cg = 0; cg < 8; cg++) s += g_part[cg * (F * D) + f * D + t];

    float q = s * s;
    #pragma unroll
    for (int o = 16; o > 0; o >>= 1) q += __shfl_xor_sync(0xffffffffu, q, o);
    if ((t & 31) == 0) red[t >> 5] = q;
    __syncthreads();
    const float ssum = (red[0] + red[1]) + (red[2] + red[3]);
    const float pinv = SCALE_L2 / fmaxf(sqrtf(ssum), 1e-9f);
    sp[t] = s * pinv;
    __syncthreads();

    // 32 uint2 half-entries for this family inside the paired uint4 layout:
    //   uint4 index: (kt*4 + (f>>4))*32 + (f&7)*4 + c ; half = (f>>3)&1
    if (t < 32) {
        const int kt = t >> 2;
        const int c  = t & 3;
        const int k0 = kt * 16 + c * 4;
        uint2 b;
        b.x = pack_bf16x2(sp[k0],     sp[k0 + 1]);
        b.y = pack_bf16x2(sp[k0 + 2], sp[k0 + 3]);
        uint2* dst = reinterpret_cast<uint2*>(g_bfrag4);
        dst[(((kt * 4 + (f >> 4)) * 32 + (f & 7) * 4 + c) << 1) + ((f >> 3) & 1)] = b;
    }
}

// ---------------- K3: fused dots + cosine + LSE + loss (+finalize), fp32 input ----------------
__global__ __launch_bounds__(256, 3) void k_loss(const float* __restrict__ emb,
                                                 const int* __restrict__ fams,
                                                 int n, float* __restrict__ out) {
    __shared__ uint4 sB[8 * 4 * 32];   // 16 KB
    __shared__ float sRed[8];
    const int t = threadIdx.x;
    for (int i = t; i < 8 * 4 * 32; i += 256) sB[i] = g_bfrag4[i];
    __syncthreads();

    const int lane = t & 31, wid = t >> 5;
    const int nwarps = gridDim.x * 8;
    const int nblocks = n >> 4;
    const int roff = (lane >> 2);
    const int koff = (lane & 3) * 4;

    float lsum = 0.0f;

    int wb = blockIdx.x * 8 + wid;
    const float* p;        // single base pointer; row+8 via immediate offset (+1024 floats)
    int f0 = 0, f1 = 0;
    float4 buf[2][2];      // [slot][row0/row1], depth-2

    if (wb < nblocks) {
        int r = (wb << 4) + roff;
        p = emb + (size_t)r * D + koff;
        f0 = fams[r]; f1 = fams[r + 8];
        #pragma unroll
        for (int q = 0; q < 2; q++) {
            buf[q][0] = *(const float4*)(p + q * 16);
            buf[q][1] = *(const float4*)(p + 1024 + q * 16);
        }
    }

    while (wb < nblocks) {
        const int wbn = wb + nwarps;
        const bool has_next = wbn < nblocks;
        const float* np = p;
        int nf0 = f0, nf1 = f1;

        float acc[8][4];
        #pragma unroll
        for (int nt = 0; nt < 8; nt++)
            #pragma unroll
            for (int j = 0; j < 4; j++) acc[nt][j] = 0.0f;

        float ss0 = 0.0f, ss1 = 0.0f;

        #pragma unroll
        for (int kt = 0; kt < 8; kt++) {
            const int sl = kt & 1;
            float4 c0 = buf[sl][0], c1 = buf[sl][1];
            if (kt < 6) {
                buf[sl][0] = *(const float4*)(p + (kt + 2) * 16);
                buf[sl][1] = *(const float4*)(p + 1024 + (kt + 2) * 16);
            } else if (has_next) {
                if (kt == 6) {
                    int rn = (wbn << 4) + roff;
                    np = emb + (size_t)rn * D + koff;
                    nf0 = fams[rn]; nf1 = fams[rn + 8];
                }
                const int q = kt - 6;
                buf[sl][0] = *(const float4*)(np + q * 16);
                buf[sl][1] = *(const float4*)(np + 1024 + q * 16);
            }
            ss0 += c0.x * c0.x + c0.y * c0.y + c0.z * c0.z + c0.w * c0.w;
            ss1 += c1.x * c1.x + c1.y * c1.y + c1.z * c1.z + c1.w * c1.w;
            unsigned a0 = pack_bf16x2(c0.x, c0.y);
            unsigned a2 = pack_bf16x2(c0.z, c0.w);
            unsigned a1 = pack_bf16x2(c1.x, c1.y);
            unsigned a3 = pack_bf16x2(c1.z, c1.w);
            #pragma unroll
            for (int m = 0; m < 4; m++) {
                uint4 b = sB[(kt * 4 + m) * 32 + lane];
                mma_bf16(acc[2 * m],     a0, a1, a2, a3, b.x, b.y);
                mma_bf16(acc[2 * m + 1], a0, a1, a2, a3, b.z, b.w);
            }
        }

        ss0 += __shfl_xor_sync(0xffffffffu, ss0, 1);
        ss0 += __shfl_xor_sync(0xffffffffu, ss0, 2);
        ss1 += __shfl_xor_sync(0xffffffffu, ss1, 1);
        ss1 += __shfl_xor_sync(0xffffffffu, ss1, 2);
        const float ie0 = rsqrtf(ss0);
        const float ie1 = rsqrtf(ss1);

        // logits in log2 units (scale pre-folded into B); |l| <= 5.78, no max-sub needed
        float pos0 = 0.0f, pos1 = 0.0f;
        float sum0 = 0.0f, sum1 = 0.0f;
        const int cbase = (lane & 3) * 2;

        #pragma unroll
        for (int nt = 0; nt < 8; nt++) {
            #pragma unroll
            for (int j = 0; j < 2; j++) {
                const int col = nt * 8 + cbase + j;
                float l0 = acc[nt][j]     * ie0;
                float l1 = acc[nt][2 + j] * ie1;
                sum0 += ex2f(l0);
                sum1 += ex2f(l1);
                if (col == f0) pos0 = l0;
                if (col == f1) pos1 = l1;
            }
        }
        pos0 += __shfl_xor_sync(0xffffffffu, pos0, 1);
        pos0 += __shfl_xor_sync(0xffffffffu, pos0, 2);
        pos1 += __shfl_xor_sync(0xffffffffu, pos1, 1);
        pos1 += __shfl_xor_sync(0xffffffffu, pos1, 2);
        sum0 += __shfl_xor_sync(0xffffffffu, sum0, 1);
        sum0 += __shfl_xor_sync(0xffffffffu, sum0, 2);
        sum1 += __shfl_xor_sync(0xffffffffu, sum1, 1);
        sum1 += __shfl_xor_sync(0xffffffffu, sum1, 2);

        if ((lane & 3) == 0) {
            lsum += (-0.5f * pos0 + __log2f(sum0))
                  + (-0.5f * pos1 + __log2f(sum1));
        }

        wb = wbn;
        p = np; f0 = nf0; f1 = nf1;
    }

    #pragma unroll
    for (int o = 16; o > 0; o >>= 1) lsum += __shfl_xor_sync(0xffffffffu, lsum, o);
    if (lane == 0) sRed[wid] = lsum;
    __syncthreads();
    if (t == 0) {
        float s = 0.0f;
        #pragma unroll
        for (int w = 0; w < 8; w++) s += sRed[w];
        atomicAdd(&g_loss, (double)s);
        __threadfence();
        int v = atomicAdd(&g_ticket, 1);
        if (v == (int)gridDim.x - 1) {
            double total = atomicAdd(&g_loss, 0.0);
            out[0] = (float)(total * LN2 / (double)n);
        }
    }
}

// ---------------- launch ----------------
extern "C" void kernel_launch(void* const* d_in, const int* in_sizes, int n_in,
                              void* d_out, int out_size) {
    const float* emb  = (const float*)d_in[0];
    const int*   fams = (const int*)d_in[1];
    const int n = in_sizes[1];
    float* out = (float*)d_out;

    k_segsum<<<NSEG, 128>>>(emb, fams, n);
    k_reduce<<<RED_CTAS, 128>>>();
    k_protos<<<F, 128>>>();
    k_loss<<<456, 256>>>(emb, fams, n, out);
}

// round 15
// speedup vs baseline: 1.3630x; 1.0344x over previous
#include <cuda_runtime.h>
#include <cuda_bf16.h>
#include <math_constants.h>
#include <cstdint>

#define D 128
#define F 64
#define NSEG 912            // 6 CTAs/SM x 152 SMs = one wave
#define RED_CTAS 512
#define CHUNK (NSEG / 8)
// 4 * log2(e): logits produced in log2 units
#define SCALE_L2 5.770780163555854f
#define LN2 0.6931471805599453

// ---------------- scratch (no allocations allowed) ----------------
__device__ float  g_stage[NSEG * F * D];
__device__ float  g_part[8 * F * D];
__device__ uint4  g_bfrag4[8 * 4 * 32];  // [kt][nt-pair][lane]: {b(2m).x,b(2m).y,b(2m+1).x,b(2m+1).y}
__device__ double g_loss;
__device__ int    g_ticket;

// ---------------- helpers ----------------
__device__ __forceinline__ unsigned pack_bf16x2(float lo, float hi) {
    unsigned r;
    asm("cvt.rn.bf16x2.f32 %0, %1, %2;" : "=r"(r) : "f"(hi), "f"(lo));
    return r;
}

__device__ __forceinline__ float ex2f(float x) {
    float r;
    asm("ex2.approx.f32 %0, %1;" : "=f"(r) : "f"(x));
    return r;
}

__device__ __forceinline__ void mma_bf16(float c[4],
                                         unsigned a0, unsigned a1, unsigned a2, unsigned a3,
                                         unsigned b0, unsigned b1) {
    asm volatile(
        "mma.sync.aligned.m16n8k16.row.col.f32.bf16.bf16.f32 "
        "{%0,%1,%2,%3}, {%4,%5,%6,%7}, {%8,%9}, {%0,%1,%2,%3};"
        : "+f"(c[0]), "+f"(c[1]), "+f"(c[2]), "+f"(c[3])
        : "r"(a0), "r"(a1), "r"(a2), "r"(a3), "r"(b0), "r"(b1));
}

// ---------------- K1: segment sums -> private slab, depth-8 prefetch ----------------
#define G 8
__global__ __launch_bounds__(128) void k_segsum(const float* __restrict__ emb,
                                                const int* __restrict__ fams,
                                                int n) {
    __shared__ float acc[F * D];
    const int t = threadIdx.x;
    #pragma unroll
    for (int i = t; i < F * D; i += 128) acc[i] = 0.0f;
    __syncthreads();

    const int stride = gridDim.x;
    int r = blockIdx.x;

    int   cf[G]; float cv[G];
    int   nf[G]; float nv[G];

    if (r + (G - 1) * stride < n) {
        #pragma unroll
        for (int j = 0; j < G; j++) {
            cf[j] = fams[r + j * stride];
            cv[j] = emb[(size_t)(r + j * stride) * D + t];
        }
        int rn = r + G * stride;
        while (rn + (G - 1) * stride < n) {
            #pragma unroll
            for (int j = 0; j < G; j++) {
                nf[j] = fams[rn + j * stride];
                nv[j] = emb[(size_t)(rn + j * stride) * D + t];
            }
            #pragma unroll
            for (int j = 0; j < G; j++) acc[cf[j] * D + t] += cv[j];
            #pragma unroll
            for (int j = 0; j < G; j++) { cf[j] = nf[j]; cv[j] = nv[j]; }
            rn += G * stride;
        }
        #pragma unroll
        for (int j = 0; j < G; j++) acc[cf[j] * D + t] += cv[j];
        r = rn;
    }
    for (; r < n; r += stride)
        acc[fams[r] * D + t] += emb[(size_t)r * D + t];

    __syncthreads();
    float* st = g_stage + (size_t)blockIdx.x * (F * D);
    #pragma unroll
    for (int i = t; i < F * D; i += 128) st[i] = acc[i];
}

// ---------------- K1b: reduce slabs -> 8 non-atomic partials ----------------
__global__ __launch_bounds__(128) void k_reduce() {
    const int t  = threadIdx.x;
    const int dg = blockIdx.x & 63;
    const int cg = blockIdx.x >> 6;
    const int base = dg * 128 + t;
    const int c0 = cg * CHUNK, c1 = c0 + CHUNK;
    float s = 0.0f;
    int c = c0;
    for (; c + 7 < c1; c += 8) {
        float v0 = g_stage[(size_t)(c + 0) * (F * D) + base];
        float v1 = g_stage[(size_t)(c + 1) * (F * D) + base];
        float v2 = g_stage[(size_t)(c + 2) * (F * D) + base];
        float v3 = g_stage[(size_t)(c + 3) * (F * D) + base];
        float v4 = g_stage[(size_t)(c + 4) * (F * D) + base];
        float v5 = g_stage[(size_t)(c + 5) * (F * D) + base];
        float v6 = g_stage[(size_t)(c + 6) * (F * D) + base];
        float v7 = g_stage[(size_t)(c + 7) * (F * D) + base];
        s += ((v0 + v1) + (v2 + v3)) + ((v4 + v5) + (v6 + v7));
    }
    for (; c < c1; c++) s += g_stage[(size_t)c * (F * D) + base];
    g_part[cg * (F * D) + base] = s;
}

// ---------------- K2: normalized protos -> paired bf16 B-fragments ----------------
// grid = 64 CTAs (one per family), 128 threads (one per dim).
// Cosine is scale-invariant: counts cancel. Fold 4*log2e/|s_f| into fragments.
__global__ __launch_bounds__(128) void k_protos() {
    __shared__ float sp[D];
    __shared__ float red[4];
    const int f = blockIdx.x;
    const int t = threadIdx.x;

    if (f == 0 && t == 0) { g_loss = 0.0; g_ticket = 0; }

    float s = 0.0f;
    #pragma unroll
    for (int cg = 0; cg < 8; cg++) s += g_part[cg * (F * D) + f * D + t];

    float q = s * s;
    #pragma unroll
    for (int o = 16; o > 0; o >>= 1) q += __shfl_xor_sync(0xffffffffu, q, o);
    if ((t & 31) == 0) red[t >> 5] = q;
    __syncthreads();
    const float ssum = (red[0] + red[1]) + (red[2] + red[3]);
    const float pinv = SCALE_L2 / fmaxf(sqrtf(ssum), 1e-9f);
    sp[t] = s * pinv;
    __syncthreads();

    // 32 uint2 half-entries for this family inside the paired uint4 layout:
    //   uint4 index: (kt*4 + (f>>4))*32 + (f&7)*4 + c ; half = (f>>3)&1
    if (t < 32) {
        const int kt = t >> 2;
        const int c  = t & 3;
        const int k0 = kt * 16 + c * 4;
        uint2 b;
        b.x = pack_bf16x2(sp[k0],     sp[k0 + 1]);
        b.y = pack_bf16x2(sp[k0 + 2], sp[k0 + 3]);
        uint2* dst = reinterpret_cast<uint2*>(g_bfrag4);
        dst[(((kt * 4 + (f >> 4)) * 32 + (f & 7) * 4 + c) << 1) + ((f >> 3) & 1)] = b;
    }
}

// ---------------- K3: fused dots + cosine + LSE + loss (+finalize), fp32 input ----------------
__global__ __launch_bounds__(256, 3) void k_loss(const float* __restrict__ emb,
                                                 const int* __restrict__ fams,
                                                 int n, float* __restrict__ out) {
    __shared__ uint4 sB[8 * 4 * 32];   // 16 KB
    __shared__ float sRed[8];
    const int t = threadIdx.x;
    for (int i = t; i < 8 * 4 * 32; i += 256) sB[i] = g_bfrag4[i];
    __syncthreads();

    const int lane = t & 31, wid = t >> 5;
    const int nwarps = gridDim.x * 8;
    const int nblocks = n >> 4;
    const int roff = (lane >> 2);
    const int koff = (lane & 3) * 4;

    float lsum = 0.0f;

    int wb = blockIdx.x * 8 + wid;
    const float* p;        // single base pointer; row+8 via immediate offset (+1024 floats)
    int f0 = 0, f1 = 0;
    float4 buf[2][2];      // [slot][row0/row1], depth-2

    if (wb < nblocks) {
        int r = (wb << 4) + roff;
        p = emb + (size_t)r * D + koff;
        f0 = fams[r]; f1 = fams[r + 8];
        #pragma unroll
        for (int q = 0; q < 2; q++) {
            buf[q][0] = *(const float4*)(p + q * 16);
            buf[q][1] = *(const float4*)(p + 1024 + q * 16);
        }
    }

    while (wb < nblocks) {
        const int wbn = wb + nwarps;
        const bool has_next = wbn < nblocks;
        const float* np = p;
        int nf0 = f0, nf1 = f1;

        float acc[8][4];
        #pragma unroll
        for (int nt = 0; nt < 8; nt++)
            #pragma unroll
            for (int j = 0; j < 4; j++) acc[nt][j] = 0.0f;

        float ss0 = 0.0f, ss1 = 0.0f;

        #pragma unroll
        for (int kt = 0; kt < 8; kt++) {
            const int sl = kt & 1;
            float4 c0 = buf[sl][0], c1 = buf[sl][1];
            if (kt < 6) {
                buf[sl][0] = *(const float4*)(p + (kt + 2) * 16);
                buf[sl][1] = *(const float4*)(p + 1024 + (kt + 2) * 16);
            } else if (has_next) {
                if (kt == 6) {
                    int rn = (wbn << 4) + roff;
                    np = emb + (size_t)rn * D + koff;
                    nf0 = fams[rn]; nf1 = fams[rn + 8];
                }
                const int q = kt - 6;
                buf[sl][0] = *(const float4*)(np + q * 16);
                buf[sl][1] = *(const float4*)(np + 1024 + q * 16);
            }
            ss0 += c0.x * c0.x + c0.y * c0.y + c0.z * c0.z + c0.w * c0.w;
            ss1 += c1.x * c1.x + c1.y * c1.y + c1.z * c1.z + c1.w * c1.w;
            unsigned a0 = pack_bf16x2(c0.x, c0.y);
            unsigned a2 = pack_bf16x2(c0.z, c0.w);
            unsigned a1 = pack_bf16x2(c1.x, c1.y);
            unsigned a3 = pack_bf16x2(c1.z, c1.w);
            #pragma unroll
            for (int m = 0; m < 4; m++) {
                uint4 b = sB[(kt * 4 + m) * 32 + lane];
                mma_bf16(acc[2 * m],     a0, a1, a2, a3, b.x, b.y);
                mma_bf16(acc[2 * m + 1], a0, a1, a2, a3, b.z, b.w);
            }
        }

        ss0 += __shfl_xor_sync(0xffffffffu, ss0, 1);
        ss0 += __shfl_xor_sync(0xffffffffu, ss0, 2);
        ss1 += __shfl_xor_sync(0xffffffffu, ss1, 1);
        ss1 += __shfl_xor_sync(0xffffffffu, ss1, 2);
        const float ie0 = rsqrtf(ss0);
        const float ie1 = rsqrtf(ss1);

        // logits in log2 units (scale pre-folded into B); |l| <= 5.78, no max-sub needed
        float pos0 = 0.0f, pos1 = 0.0f;
        float sum0 = 0.0f, sum1 = 0.0f;
        const int cbase = (lane & 3) * 2;

        #pragma unroll
        for (int nt = 0; nt < 8; nt++) {
            #pragma unroll
            for (int j = 0; j < 2; j++) {
                const int col = nt * 8 + cbase + j;
                float l0 = acc[nt][j]     * ie0;
                float l1 = acc[nt][2 + j] * ie1;
                sum0 += ex2f(l0);
                sum1 += ex2f(l1);
                if (col == f0) pos0 = l0;
                if (col == f1) pos1 = l1;
            }
        }
        pos0 += __shfl_xor_sync(0xffffffffu, pos0, 1);
        pos0 += __shfl_xor_sync(0xffffffffu, pos0, 2);
        pos1 += __shfl_xor_sync(0xffffffffu, pos1, 1);
        pos1 += __shfl_xor_sync(0xffffffffu, pos1, 2);
        sum0 += __shfl_xor_sync(0xffffffffu, sum0, 1);
        sum0 += __shfl_xor_sync(0xffffffffu, sum0, 2);
        sum1 += __shfl_xor_sync(0xffffffffu, sum1, 1);
        sum1 += __shfl_xor_sync(0xffffffffu, sum1, 2);

        if ((lane & 3) == 0) {
            lsum += (-0.5f * pos0 + __log2f(sum0))
                  + (-0.5f * pos1 + __log2f(sum1));
        }

        wb = wbn;
        p = np; f0 = nf0; f1 = nf1;
    }

    #pragma unroll
    for (int o = 16; o > 0; o >>= 1) lsum += __shfl_xor_sync(0xffffffffu, lsum, o);
    if (lane == 0) sRed[wid] = lsum;
    __syncthreads();
    if (t == 0) {
        float s = 0.0f;
        #pragma unroll
        for (int w = 0; w < 8; w++) s += sRed[w];
        atomicAdd(&g_loss, (double)s);
        __threadfence();
        int v = atomicAdd(&g_ticket, 1);
        if (v == (int)gridDim.x - 1) {
            double total = atomicAdd(&g_loss, 0.0);
            out[0] = (float)(total * LN2 / (double)n);
        }
    }
}

// ---------------- launch ----------------
extern "C" void kernel_launch(void* const* d_in, const int* in_sizes, int n_in,
                              void* d_out, int out_size) {
    const float* emb  = (const float*)d_in[0];
    const int*   fams = (const int*)d_in[1];
    const int n = in_sizes[1];
    float* out = (float*)d_out;

    k_segsum<<<NSEG, 128>>>(emb, fams, n);
    k_reduce<<<RED_CTAS, 128>>>();
    k_protos<<<F, 128>>>();
    k_loss<<<456, 256>>>(emb, fams, n, out);
}

// round 16
// speedup vs baseline: 1.3976x; 1.0254x over previous
#include <cuda_runtime.h>
#include <cuda_bf16.h>
#include <cuda_fp16.h>
#include <math_constants.h>
#include <cstdint>

#define D 128
#define F 64
#define NSEG 912            // 6 CTAs/SM x 152 SMs = one wave
#define RED_CTAS 512
#define CHUNK (NSEG / 8)
// 4 * log2(e): logits produced in log2 units
#define SCALE_L2 5.770780163555854f
#define LN2 0.6931471805599453

// ---------------- scratch (no allocations allowed) ----------------
__device__ __half g_stage[NSEG * F * D];   // fp16 slabs (15 MB; partial sums |x|<100)
__device__ float  g_part[8 * F * D];
__device__ uint4  g_bfrag4[8 * 4 * 32];  // [kt][nt-pair][lane]: {b(2m).x,b(2m).y,b(2m+1).x,b(2m+1).y}
__device__ double g_loss;
__device__ int    g_ticket;

// ---------------- helpers ----------------
__device__ __forceinline__ unsigned pack_bf16x2(float lo, float hi) {
    unsigned r;
    asm("cvt.rn.bf16x2.f32 %0, %1, %2;" : "=r"(r) : "f"(hi), "f"(lo));
    return r;
}

__device__ __forceinline__ float ex2f(float x) {
    float r;
    asm("ex2.approx.f32 %0, %1;" : "=f"(r) : "f"(x));
    return r;
}

__device__ __forceinline__ void mma_bf16(float c[4],
                                         unsigned a0, unsigned a1, unsigned a2, unsigned a3,
                                         unsigned b0, unsigned b1) {
    asm volatile(
        "mma.sync.aligned.m16n8k16.row.col.f32.bf16.bf16.f32 "
        "{%0,%1,%2,%3}, {%4,%5,%6,%7}, {%8,%9}, {%0,%1,%2,%3};"
        : "+f"(c[0]), "+f"(c[1]), "+f"(c[2]), "+f"(c[3])
        : "r"(a0), "r"(a1), "r"(a2), "r"(a3), "r"(b0), "r"(b1));
}

// ---------------- K1: segment sums -> private fp16 slab, depth-8 prefetch ----------------
#define G 8
__global__ __launch_bounds__(128) void k_segsum(const float* __restrict__ emb,
                                                const int* __restrict__ fams,
                                                int n) {
    __shared__ float acc[F * D];
    const int t = threadIdx.x;
    #pragma unroll
    for (int i = t; i < F * D; i += 128) acc[i] = 0.0f;
    __syncthreads();

    const int stride = gridDim.x;
    int r = blockIdx.x;

    int   cf[G]; float cv[G];
    int   nf[G]; float nv[G];

    if (r + (G - 1) * stride < n) {
        #pragma unroll
        for (int j = 0; j < G; j++) {
            cf[j] = fams[r + j * stride];
            cv[j] = emb[(size_t)(r + j * stride) * D + t];
        }
        int rn = r + G * stride;
        while (rn + (G - 1) * stride < n) {
            #pragma unroll
            for (int j = 0; j < G; j++) {
                nf[j] = fams[rn + j * stride];
                nv[j] = emb[(size_t)(rn + j * stride) * D + t];
            }
            #pragma unroll
            for (int j = 0; j < G; j++) acc[cf[j] * D + t] += cv[j];
            #pragma unroll
            for (int j = 0; j < G; j++) { cf[j] = nf[j]; cv[j] = nv[j]; }
            rn += G * stride;
        }
        #pragma unroll
        for (int j = 0; j < G; j++) acc[cf[j] * D + t] += cv[j];
        r = rn;
    }
    for (; r < n; r += stride)
        acc[fams[r] * D + t] += emb[(size_t)r * D + t];

    __syncthreads();
    __half* st = g_stage + (size_t)blockIdx.x * (F * D);
    #pragma unroll
    for (int i = t; i < F * D; i += 128) st[i] = __float2half_rn(acc[i]);
}

// ---------------- K1b: reduce fp16 slabs -> 8 non-atomic fp32 partials ----------------
__global__ __launch_bounds__(128) void k_reduce() {
    const int t  = threadIdx.x;
    const int dg = blockIdx.x & 63;
    const int cg = blockIdx.x >> 6;
    const int base = dg * 128 + t;
    const int c0 = cg * CHUNK, c1 = c0 + CHUNK;
    float s = 0.0f;
    int c = c0;
    for (; c + 7 < c1; c += 8) {
        float v0 = __half2float(g_stage[(size_t)(c + 0) * (F * D) + base]);
        float v1 = __half2float(g_stage[(size_t)(c + 1) * (F * D) + base]);
        float v2 = __half2float(g_stage[(size_t)(c + 2) * (F * D) + base]);
        float v3 = __half2float(g_stage[(size_t)(c + 3) * (F * D) + base]);
        float v4 = __half2float(g_stage[(size_t)(c + 4) * (F * D) + base]);
        float v5 = __half2float(g_stage[(size_t)(c + 5) * (F * D) + base]);
        float v6 = __half2float(g_stage[(size_t)(c + 6) * (F * D) + base]);
        float v7 = __half2float(g_stage[(size_t)(c + 7) * (F * D) + base]);
        s += ((v0 + v1) + (v2 + v3)) + ((v4 + v5) + (v6 + v7));
    }
    for (; c < c1; c++) s += __half2float(g_stage[(size_t)c * (F * D) + base]);
    g_part[cg * (F * D) + base] = s;
}

// ---------------- K2: normalized protos -> paired bf16 B-fragments ----------------
// grid = 64 CTAs (one per family), 128 threads (one per dim).
// Cosine is scale-invariant: counts cancel. Fold 4*log2e/|s_f| into fragments.
__global__ __launch_bounds__(128) void k_protos() {
    __shared__ float sp[D];
    __shared__ float red[4];
    const int f = blockIdx.x;
    const int t = threadIdx.x;

    if (f == 0 && t == 0) { g_loss = 0.0; g_ticket = 0; }

    float s = 0.0f;
    #pragma unroll
    for (int cg = 0; cg < 8; cg++) s += g_part[cg * (F * D) + f * D + t];

    float q = s * s;
    #pragma unroll
    for (int o = 16; o > 0; o >>= 1) q += __shfl_xor_sync(0xffffffffu, q, o);
    if ((t & 31) == 0) red[t >> 5] = q;
    __syncthreads();
    const float ssum = (red[0] + red[1]) + (red[2] + red[3]);
    const float pinv = SCALE_L2 / fmaxf(sqrtf(ssum), 1e-9f);
    sp[t] = s * pinv;
    __syncthreads();

    // 32 uint2 half-entries for this family inside the paired uint4 layout:
    //   uint4 index: (kt*4 + (f>>4))*32 + (f&7)*4 + c ; half = (f>>3)&1
    if (t < 32) {
        const int kt = t >> 2;
        const int c  = t & 3;
        const int k0 = kt * 16 + c * 4;
        uint2 b;
        b.x = pack_bf16x2(sp[k0],     sp[k0 + 1]);
        b.y = pack_bf16x2(sp[k0 + 2], sp[k0 + 3]);
        uint2* dst = reinterpret_cast<uint2*>(g_bfrag4);
        dst[(((kt * 4 + (f >> 4)) * 32 + (f & 7) * 4 + c) << 1) + ((f >> 3) & 1)] = b;
    }
}

// ---------------- K3: fused dots + cosine + LSE + loss (+finalize), fp32 input ----------------
__global__ __launch_bounds__(256, 3) void k_loss(const float* __restrict__ emb,
                                                 const int* __restrict__ fams,
                                                 int n, float* __restrict__ out) {
    __shared__ uint4 sB[8 * 4 * 32];   // 16 KB
    __shared__ float sRed[8];
    const int t = threadIdx.x;
    for (int i = t; i < 8 * 4 * 32; i += 256) sB[i] = g_bfrag4[i];
    __syncthreads();

    const int lane = t & 31, wid = t >> 5;
    const int nwarps = gridDim.x * 8;
    const int nblocks = n >> 4;
    const int roff = (lane >> 2);
    const int koff = (lane & 3) * 4;

    float lsum = 0.0f;

    int wb = blockIdx.x * 8 + wid;
    const float* p;        // single base pointer; row+8 via immediate offset (+1024 floats)
    int f0 = 0, f1 = 0;
    float4 buf[2][2];      // [slot][row0/row1], depth-2

    if (wb < nblocks) {
        int r = (wb << 4) + roff;
        p = emb + (size_t)r * D + koff;
        f0 = fams[r]; f1 = fams[r + 8];
        #pragma unroll
        for (int q = 0; q < 2; q++) {
            buf[q][0] = *(const float4*)(p + q * 16);
            buf[q][1] = *(const float4*)(p + 1024 + q * 16);
        }
    }

    while (wb < nblocks) {
        const int wbn = wb + nwarps;
        const bool has_next = wbn < nblocks;
        const float* np = p;
        int nf0 = f0, nf1 = f1;

        float acc[8][4];
        #pragma unroll
        for (int nt = 0; nt < 8; nt++)
            #pragma unroll
            for (int j = 0; j < 4; j++) acc[nt][j] = 0.0f;

        float ss0 = 0.0f, ss1 = 0.0f;

        #pragma unroll
        for (int kt = 0; kt < 8; kt++) {
            const int sl = kt & 1;
            float4 c0 = buf[sl][0], c1 = buf[sl][1];
            if (kt < 6) {
                buf[sl][0] = *(const float4*)(p + (kt + 2) * 16);
                buf[sl][1] = *(const float4*)(p + 1024 + (kt + 2) * 16);
            } else if (has_next) {
                if (kt == 6) {
                    int rn = (wbn << 4) + roff;
                    np = emb + (size_t)rn * D + koff;
                    nf0 = fams[rn]; nf1 = fams[rn + 8];
                }
                const int q = kt - 6;
                buf[sl][0] = *(const float4*)(np + q * 16);
                buf[sl][1] = *(const float4*)(np + 1024 + q * 16);
            }
            ss0 += c0.x * c0.x + c0.y * c0.y + c0.z * c0.z + c0.w * c0.w;
            ss1 += c1.x * c1.x + c1.y * c1.y + c1.z * c1.z + c1.w * c1.w;
            unsigned a0 = pack_bf16x2(c0.x, c0.y);
            unsigned a2 = pack_bf16x2(c0.z, c0.w);
            unsigned a1 = pack_bf16x2(c1.x, c1.y);
            unsigned a3 = pack_bf16x2(c1.z, c1.w);
            #pragma unroll
            for (int m = 0; m < 4; m++) {
                uint4 b = sB[(kt * 4 + m) * 32 + lane];
                mma_bf16(acc[2 * m],     a0, a1, a2, a3, b.x, b.y);
                mma_bf16(acc[2 * m + 1], a0, a1, a2, a3, b.z, b.w);
            }
        }

        ss0 += __shfl_xor_sync(0xffffffffu, ss0, 1);
        ss0 += __shfl_xor_sync(0xffffffffu, ss0, 2);
        ss1 += __shfl_xor_sync(0xffffffffu, ss1, 1);
        ss1 += __shfl_xor_sync(0xffffffffu, ss1, 2);
        const float ie0 = rsqrtf(ss0);
        const float ie1 = rsqrtf(ss1);

        // logits in log2 units (scale pre-folded into B); |l| <= 5.78, no max-sub needed
        float pos0 = 0.0f, pos1 = 0.0f;
        float sum0 = 0.0f, sum1 = 0.0f;
        const int cbase = (lane & 3) * 2;

        #pragma unroll
        for (int nt = 0; nt < 8; nt++) {
            #pragma unroll
            for (int j = 0; j < 2; j++) {
                const int col = nt * 8 + cbase + j;
                float l0 = acc[nt][j]     * ie0;
                float l1 = acc[nt][2 + j] * ie1;
                sum0 += ex2f(l0);
                sum1 += ex2f(l1);
                if (col == f0) pos0 = l0;
                if (col == f1) pos1 = l1;
            }
        }
        pos0 += __shfl_xor_sync(0xffffffffu, pos0, 1);
        pos0 += __shfl_xor_sync(0xffffffffu, pos0, 2);
        pos1 += __shfl_xor_sync(0xffffffffu, pos1, 1);
        pos1 += __shfl_xor_sync(0xffffffffu, pos1, 2);
        sum0 += __shfl_xor_sync(0xffffffffu, sum0, 1);
        sum0 += __shfl_xor_sync(0xffffffffu, sum0, 2);
        sum1 += __shfl_xor_sync(0xffffffffu, sum1, 1);
        sum1 += __shfl_xor_sync(0xffffffffu, sum1, 2);

        if ((lane & 3) == 0) {
            lsum += (-0.5f * pos0 + __log2f(sum0))
                  + (-0.5f * pos1 + __log2f(sum1));
        }

        wb = wbn;
        p = np; f0 = nf0; f1 = nf1;
    }

    #pragma unroll
    for (int o = 16; o > 0; o >>= 1) lsum += __shfl_xor_sync(0xffffffffu, lsum, o);
    if (lane == 0) sRed[wid] = lsum;
    __syncthreads();
    if (t == 0) {
        float s = 0.0f;
        #pragma unroll
        for (int w = 0; w < 8; w++) s += sRed[w];
        atomicAdd(&g_loss, (double)s);
        __threadfence();
        int v = atomicAdd(&g_ticket, 1);
        if (v == (int)gridDim.x - 1) {
            double total = atomicAdd(&g_loss, 0.0);
            out[0] = (float)(total * LN2 / (double)n);
        }
    }
}

// ---------------- launch ----------------
extern "C" void kernel_launch(void* const* d_in, const int* in_sizes, int n_in,
                              void* d_out, int out_size) {
    const float* emb  = (const float*)d_in[0];
    const int*   fams = (const int*)d_in[1];
    const int n = in_sizes[1];
    float* out = (float*)d_out;

    k_segsum<<<NSEG, 128>>>(emb, fams, n);
    k_reduce<<<RED_CTAS, 128>>>();
    k_protos<<<F, 128>>>();
    k_loss<<<456, 256>>>(emb, fams, n, out);
}